// round 1
// baseline (speedup 1.0000x reference)
#include <cuda_runtime.h>
#include <cstring>

#define NQ 8
#define DIM 256
#define NL 8
#define BATCH 65536
#define TILE_M 32

// Folded matrix V[k][n] = (Re, Im) of U[n][k] * (-i)^popcount(k).
// Layout [k][n] so the GEMM loads are coalesced across threads (thread = n).
__device__ float2 g_V[DIM * DIM];

// ---------------------------------------------------------------------------
// Kernel 1: build V from weights. One block per basis column k, 256 threads,
// state vector (256 complex) in shared memory, thread t owns amplitude t.
// ---------------------------------------------------------------------------
__global__ void build_V_kernel(const float* __restrict__ w) {
    __shared__ float2 amp[DIM];
    const int t = threadIdx.x;
    const int k = blockIdx.x;

    amp[t] = make_float2(t == k ? 1.0f : 0.0f, 0.0f);
    __syncthreads();

    for (int l = 0; l < NL; l++) {
        // RY(w[l,q,0]) then RZ(w[l,q,1]) on wire q, combined into one 2x2.
        for (int q = 0; q < NQ; q++) {
            const float th_y = w[(l * NQ + q) * 2 + 0];
            const float th_z = w[(l * NQ + q) * 2 + 1];
            const float c   = cosf(0.5f * th_y);
            const float s   = sinf(0.5f * th_y);
            const float zc  = cosf(0.5f * th_z);
            const float zs  = sinf(0.5f * th_z);
            const int mask = 1 << (7 - q);

            const float2 my    = amp[t];
            const float2 other = amp[t ^ mask];
            __syncthreads();

            float2 r;
            if (!(t & mask)) {
                // row0 of RY: c*my - s*other, then * e^{-i z/2} = (zc, -zs)
                const float xr = c * my.x - s * other.x;
                const float xi = c * my.y - s * other.y;
                r.x = zc * xr + zs * xi;
                r.y = zc * xi - zs * xr;
            } else {
                // row1 of RY: s*other + c*my, then * e^{+i z/2} = (zc, +zs)
                const float xr = s * other.x + c * my.x;
                const float xi = s * other.y + c * my.y;
                r.x = zc * xr - zs * xi;
                r.y = zc * xi + zs * xr;
            }
            amp[t] = r;
            __syncthreads();
        }
        // CNOT ring: control q, target (q+1)%8, applied sequentially.
        for (int q = 0; q < NQ; q++) {
            const int cbit = 1 << (7 - q);
            const int tq   = (q + 1) & 7;
            const int tbit = 1 << (7 - tq);
            const int src  = (t & cbit) ? (t ^ tbit) : t;
            const float2 v = amp[src];
            __syncthreads();
            amp[t] = v;
            __syncthreads();
        }
    }

    // Fold embedding phase (-i)^popcount(k) into column k.
    const float2 u = amp[t];
    const int pc = __popc(k) & 3;
    float2 vv;
    if      (pc == 0) vv = u;
    else if (pc == 1) vv = make_float2( u.y, -u.x);   // * (-i)
    else if (pc == 2) vv = make_float2(-u.x, -u.y);   // * (-1)
    else              vv = make_float2(-u.y,  u.x);   // * (+i)
    g_V[k * DIM + t] = vv;
}

// ---------------------------------------------------------------------------
// Packed fp32x2 helpers (Blackwell FFMA2).
// ---------------------------------------------------------------------------
__device__ __forceinline__ float2 ffma2(float2 a, float2 b, float2 c) {
    asm("fma.rn.f32x2 %0, %1, %2, %0;"
        : "+l"(*reinterpret_cast<unsigned long long*>(&c))
        : "l"(*reinterpret_cast<unsigned long long*>(&a)),
          "l"(*reinterpret_cast<unsigned long long*>(&b)));
    return c;
}

__device__ __forceinline__ float2 dup2(float f) {
    float2 d;
    asm("mov.b64 %0, {%1, %1};"
        : "=l"(*reinterpret_cast<unsigned long long*>(&d))
        : "f"(f));
    return d;
}

// ---------------------------------------------------------------------------
// Kernel 2: main GEMM + epilogue.
//   per CTA: TILE_M=32 samples, 256 threads (thread = output index n).
//   amp_r[n], amp_i[n] for 32 samples accumulated as 16+16 packed f32x2.
// ---------------------------------------------------------------------------
__global__ __launch_bounds__(256, 2)
void qsim_main_kernel(const float* __restrict__ x, float* __restrict__ out) {
    __shared__ float sm_cs[NQ][33];          // cos(x/2), padded rows
    __shared__ float sm_sn[NQ][33];          // sin(x/2)
    __shared__ float sm_buf[TILE_M * 257];   // m[k][s] (k*32+s), then prob[s*257+n]

    const int t  = threadIdx.x;
    const int b0 = blockIdx.x * TILE_M;

    // --- load angles: thread -> (q = t>>5, s = t&31) ---
    {
        const int q = t >> 5;
        const int s = t & 31;
        const float xv = x[(b0 + s) * NQ + q];
        sm_cs[q][s] = cosf(0.5f * xv);
        sm_sn[q][s] = sinf(0.5f * xv);
    }
    __syncthreads();

    // --- build m[k][s]: thread -> (kg = t>>5, s = t&31), k = kg*32..kg*32+31 ---
    {
        const int kg = t >> 5;
        const int s  = t & 31;
        for (int kk = 0; kk < 32; kk++) {
            const int k = kg * 32 + kk;
            float m = 1.0f;
#pragma unroll
            for (int q = 0; q < NQ; q++) {
                m *= ((k >> (7 - q)) & 1) ? sm_sn[q][s] : sm_cs[q][s];
            }
            sm_buf[k * TILE_M + s] = m;
        }
    }
    __syncthreads();

    // --- main loop: acc[n][s] over k ---
    float2 accR[16], accI[16];
#pragma unroll
    for (int j = 0; j < 16; j++) {
        accR[j] = make_float2(0.0f, 0.0f);
        accI[j] = make_float2(0.0f, 0.0f);
    }

#pragma unroll 4
    for (int k = 0; k < DIM; k++) {
        const float2 v   = g_V[k * DIM + t];        // coalesced LDG.64
        const float2 vr2 = dup2(v.x);
        const float2 vi2 = dup2(v.y);
        const float4* mrow = reinterpret_cast<const float4*>(&sm_buf[k * TILE_M]);
#pragma unroll
        for (int j = 0; j < 8; j++) {
            const float4 mv = mrow[j];              // broadcast LDS.128
            const float2 p0 = make_float2(mv.x, mv.y);
            const float2 p1 = make_float2(mv.z, mv.w);
            accR[2 * j]     = ffma2(vr2, p0, accR[2 * j]);
            accR[2 * j + 1] = ffma2(vr2, p1, accR[2 * j + 1]);
            accI[2 * j]     = ffma2(vi2, p0, accI[2 * j]);
            accI[2 * j + 1] = ffma2(vi2, p1, accI[2 * j + 1]);
        }
    }

    __syncthreads();   // done reading m; reuse sm_buf for probs

    // --- probs: prob[s][n] with row stride 257 (conflict-free) ---
#pragma unroll
    for (int j = 0; j < 16; j++) {
        const int s0 = 2 * j;
        const int s1 = 2 * j + 1;
        sm_buf[s0 * 257 + t] = accR[j].x * accR[j].x + accI[j].x * accI[j].x;
        sm_buf[s1 * 257 + t] = accR[j].y * accR[j].y + accI[j].y * accI[j].y;
    }
    __syncthreads();

    // --- signed reduction: thread -> (q = t>>5, s = t&31) ---
    {
        const int q = t >> 5;
        const int s = t & 31;
        const float* pr = &sm_buf[s * 257];
        const int shift = 7 - q;
        float acc = 0.0f;
#pragma unroll 8
        for (int n = 0; n < DIM; n++) {
            const float p = pr[n];
            acc += ((n >> shift) & 1) ? -p : p;
        }
        out[(b0 + s) * NQ + q] = acc;
    }
}

// ---------------------------------------------------------------------------
extern "C" void kernel_launch(void* const* d_in, const int* in_sizes, int n_in,
                              void* d_out, int out_size) {
    const float* x = (const float*)d_in[0];
    const float* w = (const float*)d_in[1];
    // Defensive: x is the big input (65536*8), weights is 8*8*2.
    if (n_in >= 2 && in_sizes[0] < in_sizes[1]) {
        const float* tmp = x; x = w; w = tmp;
    }
    float* out = (float*)d_out;

    build_V_kernel<<<DIM, DIM>>>(w);
    qsim_main_kernel<<<BATCH / TILE_M, 256>>>(x, out);
}

// round 3
// speedup vs baseline: 2.9245x; 2.9245x over previous
#include <cuda_runtime.h>
#include <cuda_fp16.h>
#include <cstdint>

#define NQ 8
#define DIM 256
#define NL 8
#define BATCH 65536

#define TILE_M 64            // samples per CTA
#define THREADS 512          // 16 warps: warp = (mhalf, nchunk)
#define MSTRIDE 264          // m smem row stride in halves (256 + 8 pad)
#define VSTRIDE 40           // V-chunk smem row stride in halves (32 + 8 pad)
#define SMEM_M_BYTES (TILE_M * MSTRIDE * 2)          // 33792
#define SMEM_V_BYTES (512 * VSTRIDE * 2)             // 40960
#define SMEM_TOTAL (SMEM_M_BYTES + SMEM_V_BYTES)     // 74752

// V in fp16, chunked layout: g_Vh[kc][n2][kk], kc=k>>5, kk=k&31, n2 = 2n(+1 for Im)
__device__ __half g_Vh[8 * 512 * 32];

// ---------------------------------------------------------------------------
// Kernel 1: build folded entangler matrix, write fp16 chunked layout.
// ---------------------------------------------------------------------------
__global__ void build_V_kernel(const float* __restrict__ w) {
    __shared__ float2 amp[DIM];
    const int t = threadIdx.x;
    const int k = blockIdx.x;

    amp[t] = make_float2(t == k ? 1.0f : 0.0f, 0.0f);
    __syncthreads();

    for (int l = 0; l < NL; l++) {
        for (int q = 0; q < NQ; q++) {
            const float th_y = w[(l * NQ + q) * 2 + 0];
            const float th_z = w[(l * NQ + q) * 2 + 1];
            const float c  = cosf(0.5f * th_y);
            const float s  = sinf(0.5f * th_y);
            const float zc = cosf(0.5f * th_z);
            const float zs = sinf(0.5f * th_z);
            const int mask = 1 << (7 - q);

            const float2 my    = amp[t];
            const float2 other = amp[t ^ mask];
            __syncthreads();

            float2 r;
            if (!(t & mask)) {
                const float xr = c * my.x - s * other.x;
                const float xi = c * my.y - s * other.y;
                r.x = zc * xr + zs * xi;
                r.y = zc * xi - zs * xr;
            } else {
                const float xr = s * other.x + c * my.x;
                const float xi = s * other.y + c * my.y;
                r.x = zc * xr - zs * xi;
                r.y = zc * xi + zs * xr;
            }
            amp[t] = r;
            __syncthreads();
        }
        for (int q = 0; q < NQ; q++) {
            const int cbit = 1 << (7 - q);
            const int tq   = (q + 1) & 7;
            const int tbit = 1 << (7 - tq);
            const int src  = (t & cbit) ? (t ^ tbit) : t;
            const float2 v = amp[src];
            __syncthreads();
            amp[t] = v;
            __syncthreads();
        }
    }

    const float2 u = amp[t];
    const int pc = __popc(k) & 3;
    float2 vv;
    if      (pc == 0) vv = u;
    else if (pc == 1) vv = make_float2( u.y, -u.x);
    else if (pc == 2) vv = make_float2(-u.x, -u.y);
    else              vv = make_float2(-u.y,  u.x);

    const int kc = k >> 5, kk = k & 31;
    g_Vh[(kc * 512 + 2 * t)     * 32 + kk] = __float2half(vv.x);
    g_Vh[(kc * 512 + 2 * t + 1) * 32 + kk] = __float2half(vv.y);
}

// ---------------------------------------------------------------------------
// Tensor-core helpers
// ---------------------------------------------------------------------------
__device__ __forceinline__ uint32_t smem_u32(const void* p) {
    return (uint32_t)__cvta_generic_to_shared(p);
}

__device__ __forceinline__ void ldsm4(uint32_t r[4], uint32_t addr) {
    asm volatile("ldmatrix.sync.aligned.m8n8.x4.shared.b16 {%0,%1,%2,%3}, [%4];"
                 : "=r"(r[0]), "=r"(r[1]), "=r"(r[2]), "=r"(r[3]) : "r"(addr));
}

__device__ __forceinline__ void mma16816(float4& c, const uint32_t a[4],
                                         uint32_t b0, uint32_t b1) {
    asm volatile(
        "mma.sync.aligned.m16n8k16.row.col.f32.f16.f16.f32 "
        "{%0,%1,%2,%3}, {%4,%5,%6,%7}, {%8,%9}, {%0,%1,%2,%3};"
        : "+f"(c.x), "+f"(c.y), "+f"(c.z), "+f"(c.w)
        : "r"(a[0]), "r"(a[1]), "r"(a[2]), "r"(a[3]), "r"(b0), "r"(b1));
}

// ---------------------------------------------------------------------------
// Kernel 2: fused mma GEMM + epilogue.
//   C[64 samples x 512 cols] = m[64 x 256] * V[256 x 512] in fp16->fp32 mma,
//   cols interleave (Re, Im); prob = Re^2+Im^2; out = signed reductions.
// ---------------------------------------------------------------------------
__global__ __launch_bounds__(THREADS, 1)
void qsim_main_kernel(const float* __restrict__ x, float* __restrict__ out) {
    extern __shared__ __align__(16) char smem_raw[];
    __half* m_sm  = (__half*)smem_raw;                       // [64][MSTRIDE]
    __half* v_sm  = (__half*)(smem_raw + SMEM_M_BYTES);      // [512][VSTRIDE]
    float*  ang   = (float*)(smem_raw + SMEM_M_BYTES);       // overlay: cs/sn
    float*  outSm = (float*)(smem_raw + SMEM_M_BYTES);       // overlay: [64][8]

    const int t  = threadIdx.x;
    const int b0 = blockIdx.x * TILE_M;

    // --- angles: thread -> (s = t>>3, q = t&7), coalesced x load ---
    {
        const int s = t >> 3, q = t & 7;
        const float xv = x[(b0 + s) * NQ + q];
        float sv, cv;
        sincosf(0.5f * xv, &sv, &cv);
        ang[q * 64 + s]       = cv;
        ang[512 + q * 64 + s] = sv;
    }
    __syncthreads();

    // --- build m tile in fp16: thread -> (s = t>>3, kg = t&7), 32 k each ---
    {
        const int s = t >> 3, kg = t & 7;
        float c[NQ], sn[NQ];
#pragma unroll
        for (int q = 0; q < NQ; q++) {
            c[q]  = ang[q * 64 + s];
            sn[q] = ang[512 + q * 64 + s];
        }
        __half* mrow = m_sm + s * MSTRIDE;
#pragma unroll 4
        for (int kk = 0; kk < 32; kk += 2) {
            const int k0 = kg * 32 + kk;
            float mb = 1.0f;
#pragma unroll
            for (int q = 0; q < 7; q++)
                mb *= ((k0 >> (7 - q)) & 1) ? sn[q] : c[q];
            const float m0 = mb * c[7];
            const float m1 = mb * sn[7];
            *(__half2*)(mrow + k0) = __floats2half2_rn(m0, m1);
        }
    }
    // (K-loop top __syncthreads covers m/ang ordering)

    const int warp = t >> 5, lane = t & 31;
    const int mh   = warp & 1;        // which 32-sample half
    const int nch  = warp >> 1;       // n2 chunk of 64: [nch*64, nch*64+64)
    const int gid  = lane >> 2, tig = lane & 3;

    const uint32_t m_u = smem_u32(m_sm);
    const uint32_t v_u = smem_u32(v_sm);

    // ldmatrix per-lane row-address offsets (in halves)
    const int rowA_off = (mh * 32 + (lane & 7) + 8 * ((lane >> 3) & 1)) * MSTRIDE
                       + 8 * (lane >> 4);
    const int rowB_off = (nch * 64 + ((lane >> 4) & 1) * 8 + (lane & 7)) * VSTRIDE
                       + 8 * ((lane >> 3) & 1);

    float4 acc[2][8];
#pragma unroll
    for (int ms = 0; ms < 2; ms++)
#pragma unroll
        for (int nt = 0; nt < 8; nt++)
            acc[ms][nt] = make_float4(0.f, 0.f, 0.f, 0.f);

    // --- K loop: 8 chunks of 32 ---
    for (int kc = 0; kc < 8; kc++) {
        __syncthreads();
        // stage V chunk (32 KB) coalesced from chunked global layout
        const float4* src = (const float4*)(g_Vh + kc * (512 * 32));
#pragma unroll
        for (int j = 0; j < 4; j++) {
            const int e  = t + THREADS * j;   // 0..2047 float4's
            const int n2 = e >> 2, k8 = e & 3;
            *(float4*)(v_sm + n2 * VSTRIDE + k8 * 8) = src[e];
        }
        __syncthreads();

#pragma unroll
        for (int kb = 0; kb < 32; kb += 16) {
            const int kA = kc * 32 + kb;   // <-- FIX: A advances with kc
            uint32_t a[2][4];
            ldsm4(a[0], m_u + (uint32_t)(rowA_off + 0 * 16 * MSTRIDE + kA) * 2u);
            ldsm4(a[1], m_u + (uint32_t)(rowA_off + 1 * 16 * MSTRIDE + kA) * 2u);
#pragma unroll
            for (int nt2 = 0; nt2 < 4; nt2++) {
                uint32_t b[4];
                ldsm4(b, v_u + (uint32_t)(rowB_off + nt2 * 16 * VSTRIDE + kb) * 2u);
                mma16816(acc[0][2 * nt2],     a[0], b[0], b[1]);
                mma16816(acc[0][2 * nt2 + 1], a[0], b[2], b[3]);
                mma16816(acc[1][2 * nt2],     a[1], b[0], b[1]);
                mma16816(acc[1][2 * nt2 + 1], a[1], b[2], b[3]);
            }
        }
    }

    // --- epilogue ---
    __syncthreads();            // all warps done with v_sm
    outSm[t] = 0.0f;            // 512 floats = 64x8
    __syncthreads();

    float aq[2][2][NQ];
#pragma unroll
    for (int ms = 0; ms < 2; ms++)
#pragma unroll
        for (int h = 0; h < 2; h++)
#pragma unroll
            for (int q = 0; q < NQ; q++) aq[ms][h][q] = 0.0f;

#pragma unroll
    for (int ms = 0; ms < 2; ms++) {
#pragma unroll
        for (int nt = 0; nt < 8; nt++) {
            const float4 c = acc[ms][nt];
            const float plo = c.x * c.x + c.y * c.y;   // amplitude row gid
            const float phi = c.z * c.z + c.w * c.w;   // amplitude row gid+8
            const int n = nch * 32 + nt * 4 + tig;     // amplitude index
#pragma unroll
            for (int q = 0; q < NQ; q++) {
                const float sg = ((n >> (7 - q)) & 1) ? -1.0f : 1.0f;
                aq[ms][0][q] += sg * plo;
                aq[ms][1][q] += sg * phi;
            }
        }
    }

#pragma unroll
    for (int ms = 0; ms < 2; ms++)
#pragma unroll
        for (int h = 0; h < 2; h++)
#pragma unroll
            for (int q = 0; q < NQ; q++) {
                float v = aq[ms][h][q];
                v += __shfl_xor_sync(0xffffffffu, v, 1);
                v += __shfl_xor_sync(0xffffffffu, v, 2);
                if (tig == 0) {
                    const int row = mh * 32 + ms * 16 + h * 8 + gid;
                    atomicAdd(&outSm[row * NQ + q], v);
                }
            }

    __syncthreads();
    {
        const int s = t >> 3, q = t & 7;
        out[(b0 + s) * NQ + q] = outSm[t];
    }
}

// ---------------------------------------------------------------------------
extern "C" void kernel_launch(void* const* d_in, const int* in_sizes, int n_in,
                              void* d_out, int out_size) {
    const float* x = (const float*)d_in[0];
    const float* w = (const float*)d_in[1];
    if (n_in >= 2 && in_sizes[0] < in_sizes[1]) {
        const float* tmp = x; x = w; w = tmp;
    }
    float* out = (float*)d_out;

    cudaFuncSetAttribute(qsim_main_kernel,
                         cudaFuncAttributeMaxDynamicSharedMemorySize, SMEM_TOTAL);

    build_V_kernel<<<DIM, DIM>>>(w);
    qsim_main_kernel<<<BATCH / TILE_M, THREADS, SMEM_TOTAL>>>(x, out);
}